// round 9
// baseline (speedup 1.0000x reference)
#include <cuda_runtime.h>
#include <cuda_fp16.h>

#define NN 50000
#define NE 1600000
#define NP (NE / 2)              // 800000 edge pairs
#define NG 64
#define CAP 128                  // per-node bin capacity (Poisson(32): P(>=127) ~ 1e-43)
#define NIB ((NN + 255) / 256)   // init blocks

// ---------------- scratch (static device globals; no allocation) ----------------
__device__ __align__(16) __half g_xl1h[NN * 64];
__device__ __align__(16) __half g_xl2h[NN * 128];
__device__ float g_as1[NN * 2];
__device__ float g_ad1[NN * 2];
__device__ float g_h1[NN * 64];
__device__ float g_as2[NN];
__device__ float g_ad2[NN];
__device__ int   g_cur[NN];            // per-node count (starts at 1: self loop)
__device__ int   g_srcs[NN * CAP];     // binned adjacency, 25.6 MB
__device__ __align__(16) float4 g_e1[NN * CAP];  // {src_bits, p0, p1, -} ; reused as float2 for layer 2
__device__ float g_pool[NG * 128];
__device__ int   g_cnt[NG];
__device__ int   g_is64;

// ---------------- f32x2 packed helpers ----------------
__device__ __forceinline__ unsigned long long pk2(float x, float y) {
    unsigned long long r;
    asm("mov.b64 %0,{%1,%2};" : "=l"(r) : "f"(x), "f"(y));
    return r;
}
__device__ __forceinline__ float2 upk2(unsigned long long v) {
    float x, y;
    asm("mov.b64 {%0,%1},%2;" : "=f"(x), "=f"(y) : "l"(v));
    return make_float2(x, y);
}
__device__ __forceinline__ unsigned long long ffma2(unsigned long long a,
                                                    unsigned long long b,
                                                    unsigned long long c) {
    unsigned long long d;
    asm("fma.rn.f32x2 %0,%1,%2,%3;" : "=l"(d) : "l"(a), "l"(b), "l"(c));
    return d;
}

__device__ __forceinline__ int idx_at(const void* p, int i) {
    if (g_is64) return (int)((const long long*)p)[i];
    return ((const int*)p)[i];
}
__device__ __forceinline__ float lrelu(float e) { return fmaxf(e, 0.2f * e); }

// ---------------- init: seed self-loops, zero pool/cnt, dtype detect ------------
__global__ void k_init(const int* __restrict__ ei32) {
    int i = blockIdx.x * 256 + threadIdx.x;
    if (i < NN) {
        g_cur[i] = 1;
        g_srcs[i * CAP] = i;      // self loop in slot 0
    }
    if (i < NG * 128) g_pool[i] = 0.f;
    if (i < NG) g_cnt[i] = 0;
    if (i == 0) {
        int ok = 1;
        for (int k = 0; k < 64; k++)
            if (ei32[2 * k + 1] != 0) ok = 0;
        g_is64 = ok;
    }
}

// ---------------- direct binned scatter (no histogram, no scan) -----------------
__global__ void k_fill(const void* __restrict__ ei) {
    int t = blockIdx.x * 256 + threadIdx.x;
    if (t >= NP) return;
    int s0, s1, d0, d1;
    if (g_is64) {
        longlong2 sv = ((const longlong2*)ei)[t];
        longlong2 dv = ((const longlong2*)((const long long*)ei + NE))[t];
        s0 = (int)sv.x; s1 = (int)sv.y; d0 = (int)dv.x; d1 = (int)dv.y;
    } else {
        int2 sv = ((const int2*)ei)[t];
        int2 dv = ((const int2*)((const int*)ei + NE))[t];
        s0 = sv.x; s1 = sv.y; d0 = dv.x; d1 = dv.y;
    }
    int p0 = atomicAdd(&g_cur[d0], 1);
    g_srcs[d0 * CAP + p0] = s0;
    int p1 = atomicAdd(&g_cur[d1], 1);
    g_srcs[d1 * CAP + p1] = s1;
}

// ---------------- layer 1 GEMM: xl1 = x @ W1 (+ attention scores), fp16 out -----
__global__ void k_gemm1(const float* __restrict__ x, const float* __restrict__ W1,
                        const float* __restrict__ as, const float* __restrict__ ad) {
    __shared__ float xsh[16 * 128];
    int tid = threadIdx.x;
    int base = blockIdx.x * 16;
    {
        float4* d4 = (float4*)xsh;
        const float4* s4 = (const float4*)(x + (long)base * 128);
        for (int i = tid; i < 512; i += 128) d4[i] = s4[i];
    }
    __syncthreads();
    int nl = tid >> 4, t4 = tid & 15;
    const ulonglong2* W4 = (const ulonglong2*)W1;   // {w01,w23} packed f32x2 pairs
    unsigned long long aA0 = 0, aA1 = 0, aB0 = 0, aB1 = 0;
    const float* xa = &xsh[nl * 128];
    const float* xb = &xsh[(nl + 8) * 128];
    #pragma unroll 4
    for (int k = 0; k < 128; k++) {
        ulonglong2 w = W4[k * 16 + t4];
        unsigned long long va = pk2(xa[k], xa[k]);
        unsigned long long vb = pk2(xb[k], xb[k]);
        aA0 = ffma2(va, w.x, aA0); aA1 = ffma2(va, w.y, aA1);
        aB0 = ffma2(vb, w.x, aB0); aB1 = ffma2(vb, w.y, aB1);
    }
    float2 A0 = upk2(aA0), A1 = upk2(aA1), B0 = upk2(aB0), B1 = upk2(aB1);
    int nA = base + nl, nB = base + nl + 8;
    {
        __half2 a01 = __floats2half2_rn(A0.x, A0.y);
        __half2 a23 = __floats2half2_rn(A1.x, A1.y);
        __half2 b01 = __floats2half2_rn(B0.x, B0.y);
        __half2 b23 = __floats2half2_rn(B1.x, B1.y);
        uint2 pa, pb;
        pa.x = *(unsigned*)&a01; pa.y = *(unsigned*)&a23;
        pb.x = *(unsigned*)&b01; pb.y = *(unsigned*)&b23;
        ((uint2*)g_xl1h)[nA * 16 + t4] = pa;
        ((uint2*)g_xl1h)[nB * 16 + t4] = pb;
    }
    float4 a = ((const float4*)as)[t4];
    float4 d = ((const float4*)ad)[t4];
    float psA = A0.x * a.x + A0.y * a.y + A1.x * a.z + A1.y * a.w;
    float pdA = A0.x * d.x + A0.y * d.y + A1.x * d.z + A1.y * d.w;
    float psB = B0.x * a.x + B0.y * a.y + B1.x * a.z + B1.y * a.w;
    float pdB = B0.x * d.x + B0.y * d.y + B1.x * d.z + B1.y * d.w;
    #pragma unroll
    for (int o = 1; o < 8; o <<= 1) {
        psA += __shfl_xor_sync(0xffffffffu, psA, o);
        pdA += __shfl_xor_sync(0xffffffffu, pdA, o);
        psB += __shfl_xor_sync(0xffffffffu, psB, o);
        pdB += __shfl_xor_sync(0xffffffffu, pdB, o);
    }
    if ((t4 & 7) == 0) {
        int h = t4 >> 3;
        g_as1[nA * 2 + h] = psA;  g_ad1[nA * 2 + h] = pdA;
        g_as1[nB * 2 + h] = psB;  g_ad1[nB * 2 + h] = pdB;
    }
}

// ---------------- layer 1 score precompute: p = exp(lrelu(as+ad)) per edge ------
// warp per node; lane per edge slot. Writes {src_bits, p0, p1, 0} at bin slot.
__global__ void k_score1() {
    int n = blockIdx.x * 8 + (threadIdx.x >> 5);
    int lane = threadIdx.x & 31;
    int cnt = g_cur[n];
    float2 ad = ((const float2*)g_ad1)[n];
    int base = n * CAP;
    for (int j = lane; j < cnt; j += 32) {
        int src = g_srcs[base + j];
        float2 q = ((const float2*)g_as1)[src];
        float p0 = __expf(lrelu(q.x + ad.x));
        float p1 = __expf(lrelu(q.y + ad.y));
        g_e1[base + j] = make_float4(__int_as_float(src), p0, p1, 0.f);
    }
}

// ---------------- layer 1 aggregation: 1 warp/node, 4-edge, packed records ------
__global__ void k_agg1(const float* __restrict__ b1) {
    int n = blockIdx.x * 8 + (threadIdx.x >> 5);
    int lane = threadIdx.x & 31;
    bool h0 = lane < 16;
    float s = 0.f;
    unsigned long long acc = 0;
    const float4* E = &g_e1[n * CAP];
    int cnt = g_cur[n];
    const __half2* X = (const __half2*)g_xl1h;   // row = 32 half2
    int j = 0;
    for (; j + 3 < cnt; j += 4) {
        float4 e0 = E[j], e1 = E[j + 1], e2 = E[j + 2], e3 = E[j + 3];
        int s0 = __float_as_int(e0.x), s1 = __float_as_int(e1.x);
        int s2 = __float_as_int(e2.x), s3 = __float_as_int(e3.x);
        __half2 x0 = X[s0 * 32 + lane];
        __half2 x1 = X[s1 * 32 + lane];
        __half2 x2 = X[s2 * 32 + lane];
        __half2 x3 = X[s3 * 32 + lane];
        float p0 = h0 ? e0.y : e0.z;
        float p1 = h0 ? e1.y : e1.z;
        float p2 = h0 ? e2.y : e2.z;
        float p3 = h0 ? e3.y : e3.z;
        s += (p0 + p1) + (p2 + p3);
        float2 f0 = __half22float2(x0), f1 = __half22float2(x1);
        float2 f2 = __half22float2(x2), f3 = __half22float2(x3);
        acc = ffma2(pk2(p0, p0), pk2(f0.x, f0.y), acc);
        acc = ffma2(pk2(p1, p1), pk2(f1.x, f1.y), acc);
        acc = ffma2(pk2(p2, p2), pk2(f2.x, f2.y), acc);
        acc = ffma2(pk2(p3, p3), pk2(f3.x, f3.y), acc);
    }
    for (; j < cnt; j++) {
        float4 e0 = E[j];
        int s0 = __float_as_int(e0.x);
        __half2 x0 = X[s0 * 32 + lane];
        float p0 = h0 ? e0.y : e0.z;
        s += p0;
        float2 f0 = __half22float2(x0);
        acc = ffma2(pk2(p0, p0), pk2(f0.x, f0.y), acc);
    }
    float inv = 1.f / s;
    float2 u = upk2(acc);
    float2 bb = ((const float2*)b1)[lane];
    float o0 = u.x * inv + bb.x;
    float o1 = u.y * inv + bb.y;
    o0 = o0 > 0.f ? o0 : (__expf(o0) - 1.f);
    o1 = o1 > 0.f ? o1 : (__expf(o1) - 1.f);
    ((float2*)g_h1)[n * 32 + lane] = make_float2(o0, o1);
}

// ---------------- layer 2 GEMM: xl2 = h1 @ W2 (+ scores), fp16 out ----------------
__global__ void k_gemm2(const float* __restrict__ W2, const float* __restrict__ as,
                        const float* __restrict__ ad) {
    __shared__ float hsh[8 * 64];
    int tid = threadIdx.x;
    int base = blockIdx.x * 8;
    {
        float4* d4 = (float4*)hsh;
        const float4* s4 = (const float4*)(g_h1 + (long)base * 64);
        if (tid < 128) d4[tid] = s4[tid];
    }
    __syncthreads();
    int nl = tid >> 5, t = tid & 31;
    const ulonglong2* W4 = (const ulonglong2*)W2;
    unsigned long long aA0 = 0, aA1 = 0, aB0 = 0, aB1 = 0;
    const float* xa = &hsh[nl * 64];
    const float* xb = &hsh[(nl + 4) * 64];
    #pragma unroll 4
    for (int k = 0; k < 64; k++) {
        ulonglong2 w = W4[k * 32 + t];
        unsigned long long va = pk2(xa[k], xa[k]);
        unsigned long long vb = pk2(xb[k], xb[k]);
        aA0 = ffma2(va, w.x, aA0); aA1 = ffma2(va, w.y, aA1);
        aB0 = ffma2(vb, w.x, aB0); aB1 = ffma2(vb, w.y, aB1);
    }
    float2 A0 = upk2(aA0), A1 = upk2(aA1), B0 = upk2(aB0), B1 = upk2(aB1);
    int nA = base + nl, nB = base + nl + 4;
    {
        __half2 a01 = __floats2half2_rn(A0.x, A0.y);
        __half2 a23 = __floats2half2_rn(A1.x, A1.y);
        __half2 b01 = __floats2half2_rn(B0.x, B0.y);
        __half2 b23 = __floats2half2_rn(B1.x, B1.y);
        uint2 pa, pb;
        pa.x = *(unsigned*)&a01; pa.y = *(unsigned*)&a23;
        pb.x = *(unsigned*)&b01; pb.y = *(unsigned*)&b23;
        ((uint2*)g_xl2h)[nA * 32 + t] = pa;
        ((uint2*)g_xl2h)[nB * 32 + t] = pb;
    }
    float4 a = ((const float4*)as)[t];
    float4 d = ((const float4*)ad)[t];
    float psA = A0.x * a.x + A0.y * a.y + A1.x * a.z + A1.y * a.w;
    float pdA = A0.x * d.x + A0.y * d.y + A1.x * d.z + A1.y * d.w;
    float psB = B0.x * a.x + B0.y * a.y + B1.x * a.z + B1.y * a.w;
    float pdB = B0.x * d.x + B0.y * d.y + B1.x * d.z + B1.y * d.w;
    #pragma unroll
    for (int o = 1; o < 32; o <<= 1) {
        psA += __shfl_xor_sync(0xffffffffu, psA, o);
        pdA += __shfl_xor_sync(0xffffffffu, pdA, o);
        psB += __shfl_xor_sync(0xffffffffu, psB, o);
        pdB += __shfl_xor_sync(0xffffffffu, pdB, o);
    }
    if (t == 0) {
        g_as2[nA] = psA; g_ad2[nA] = pdA;
        g_as2[nB] = psB; g_ad2[nB] = pdB;
    }
}

// ---------------- layer 2 score precompute: {src_bits, p} per edge --------------
__global__ void k_score2() {
    int n = blockIdx.x * 8 + (threadIdx.x >> 5);
    int lane = threadIdx.x & 31;
    int cnt = g_cur[n];
    float ad = g_ad2[n];
    int base = n * CAP;
    float2* E2 = (float2*)g_e1;
    for (int j = lane; j < cnt; j += 32) {
        int src = g_srcs[base + j];
        float p = __expf(lrelu(g_as2[src] + ad));
        E2[base + j] = make_float2(__int_as_float(src), p);
    }
}

// ---------------- layer 2 aggregation: 2 warps/node, 4-edge, packed records -----
__global__ void k_agg2(const float* __restrict__ b2, const void* __restrict__ batch) {
    int t = threadIdx.x;
    int n = blockIdx.x * 4 + (t >> 6);
    int w = (t >> 5) & 1;
    int lane = t & 31;
    int col = w * 32 + lane;                      // half2 index within row
    float s = 0.f;
    unsigned long long acc = 0;
    const float2* E = (const float2*)g_e1 + n * CAP;
    int cnt = g_cur[n];
    const __half2* X = (const __half2*)g_xl2h;    // row = 64 half2
    int j = 0;
    for (; j + 3 < cnt; j += 4) {
        float2 e0 = E[j], e1 = E[j + 1], e2 = E[j + 2], e3 = E[j + 3];
        int s0 = __float_as_int(e0.x), s1 = __float_as_int(e1.x);
        int s2 = __float_as_int(e2.x), s3 = __float_as_int(e3.x);
        __half2 x0 = X[s0 * 64 + col];
        __half2 x1 = X[s1 * 64 + col];
        __half2 x2 = X[s2 * 64 + col];
        __half2 x3 = X[s3 * 64 + col];
        s += (e0.y + e1.y) + (e2.y + e3.y);
        float2 f0 = __half22float2(x0), f1 = __half22float2(x1);
        float2 f2 = __half22float2(x2), f3 = __half22float2(x3);
        acc = ffma2(pk2(e0.y, e0.y), pk2(f0.x, f0.y), acc);
        acc = ffma2(pk2(e1.y, e1.y), pk2(f1.x, f1.y), acc);
        acc = ffma2(pk2(e2.y, e2.y), pk2(f2.x, f2.y), acc);
        acc = ffma2(pk2(e3.y, e3.y), pk2(f3.x, f3.y), acc);
    }
    for (; j < cnt; j++) {
        float2 e0 = E[j];
        int s0 = __float_as_int(e0.x);
        __half2 x0 = X[s0 * 64 + col];
        s += e0.y;
        float2 f0 = __half22float2(x0);
        acc = ffma2(pk2(e0.y, e0.y), pk2(f0.x, f0.y), acc);
    }
    float inv = 1.f / s;
    float2 u = upk2(acc);
    float2 bb = ((const float2*)b2)[col];
    float v0 = u.x * inv + bb.x; v0 = v0 > 0.f ? v0 : (__expf(v0) - 1.f);
    float v1 = u.y * inv + bb.y; v1 = v1 > 0.f ? v1 : (__expf(v1) - 1.f);
    int b = idx_at(batch, n);
    float* pp = &g_pool[b * 128 + col * 2];
    atomicAdd(pp + 0, v0);
    atomicAdd(pp + 1, v1);
    if (col == 0) atomicAdd(&g_cnt[b], 1);
}

// ---------------- final: mean pool -> out ----------------
__global__ void k_final(float* __restrict__ out) {
    int i = blockIdx.x * 256 + threadIdx.x;
    if (i < NG * 128) {
        int g = i >> 7;
        out[i] = g_pool[i] / fmaxf((float)g_cnt[g], 1.f);
    }
}

extern "C" void kernel_launch(void* const* d_in, const int* in_sizes, int n_in,
                              void* d_out, int out_size) {
    const float* x   = (const float*)d_in[0];
    const void*  ei  = d_in[1];
    const void*  bat = d_in[2];
    const float* W1  = (const float*)d_in[3];
    const float* as1 = (const float*)d_in[4];
    const float* ad1 = (const float*)d_in[5];
    const float* b1  = (const float*)d_in[6];
    const float* W2  = (const float*)d_in[7];
    const float* as2 = (const float*)d_in[8];
    const float* ad2 = (const float*)d_in[9];
    const float* b2  = (const float*)d_in[10];
    float* out = (float*)d_out;

    k_init<<<NIB, 256>>>((const int*)ei);            // #0
    k_gemm1<<<NN / 16, 128>>>(x, W1, as1, ad1);      // #1
    k_fill<<<(NP + 255) / 256, 256>>>(ei);           // #2
    k_score1<<<NN / 8, 256>>>();                     // #3 <-- profiled
    k_agg1<<<NN / 8, 256>>>(b1);                     // #4
    k_gemm2<<<NN / 8, 128>>>(W2, as2, ad2);          // #5
    k_score2<<<NN / 8, 256>>>();                     // #6
    k_agg2<<<NN / 4, 256>>>(b2, bat);                // #7
    k_final<<<32, 256>>>(out);                       // #8
}

// round 10
// speedup vs baseline: 1.0310x; 1.0310x over previous
#include <cuda_runtime.h>
#include <cuda_fp16.h>

#define NN 50000
#define NE 1600000
#define NP (NE / 2)              // 800000 edge pairs
#define NG 64
#define CAP 128                  // per-node bin capacity (Poisson(32): P(>=127) ~ 1e-43)
#define NIB ((NN + 255) / 256)   // init blocks

// ---------------- scratch (static device globals; no allocation) ----------------
__device__ __align__(16) __half g_xl1h[NN * 64];
__device__ __align__(16) __half g_xl2h[NN * 128];
__device__ float g_as1[NN * 2];
__device__ float g_ad1[NN * 2];
__device__ float g_h1[NN * 64];
__device__ float g_as2[NN];
__device__ float g_ad2[NN];
__device__ int   g_cur[NN];          // per-node count (starts at 1: self loop)
__device__ __align__(16) int g_srcs[NN * CAP];   // binned adjacency, 25.6 MB
__device__ float g_pool[NG * 128];
__device__ int   g_cnt[NG];
__device__ int   g_is64;

// ---------------- f32x2 packed helpers ----------------
__device__ __forceinline__ unsigned long long pk2(float x, float y) {
    unsigned long long r;
    asm("mov.b64 %0,{%1,%2};" : "=l"(r) : "f"(x), "f"(y));
    return r;
}
__device__ __forceinline__ float2 upk2(unsigned long long v) {
    float x, y;
    asm("mov.b64 {%0,%1},%2;" : "=f"(x), "=f"(y) : "l"(v));
    return make_float2(x, y);
}
__device__ __forceinline__ unsigned long long ffma2(unsigned long long a,
                                                    unsigned long long b,
                                                    unsigned long long c) {
    unsigned long long d;
    asm("fma.rn.f32x2 %0,%1,%2,%3;" : "=l"(d) : "l"(a), "l"(b), "l"(c));
    return d;
}

__device__ __forceinline__ int idx_at(const void* p, int i) {
    if (g_is64) return (int)((const long long*)p)[i];
    return ((const int*)p)[i];
}
__device__ __forceinline__ float lrelu(float e) { return fmaxf(e, 0.2f * e); }

// ---------------- init: seed self-loops, zero pool/cnt, dtype detect ------------
__global__ void k_init(const int* __restrict__ ei32) {
    int i = blockIdx.x * 256 + threadIdx.x;
    if (i < NN) {
        g_cur[i] = 1;
        g_srcs[i * CAP] = i;      // self loop in slot 0
    }
    if (i < NG * 128) g_pool[i] = 0.f;
    if (i < NG) g_cnt[i] = 0;
    if (i == 0) {
        int ok = 1;
        for (int k = 0; k < 64; k++)
            if (ei32[2 * k + 1] != 0) ok = 0;
        g_is64 = ok;
    }
}

// ---------------- direct binned scatter (no histogram, no scan) -----------------
__global__ void k_fill(const void* __restrict__ ei) {
    int t = blockIdx.x * 256 + threadIdx.x;
    if (t >= NP) return;
    int s0, s1, d0, d1;
    if (g_is64) {
        longlong2 sv = ((const longlong2*)ei)[t];
        longlong2 dv = ((const longlong2*)((const long long*)ei + NE))[t];
        s0 = (int)sv.x; s1 = (int)sv.y; d0 = (int)dv.x; d1 = (int)dv.y;
    } else {
        int2 sv = ((const int2*)ei)[t];
        int2 dv = ((const int2*)((const int*)ei + NE))[t];
        s0 = sv.x; s1 = sv.y; d0 = dv.x; d1 = dv.y;
    }
    int p0 = atomicAdd(&g_cur[d0], 1);
    g_srcs[d0 * CAP + p0] = s0;
    int p1 = atomicAdd(&g_cur[d1], 1);
    g_srcs[d1 * CAP + p1] = s1;
}

// ---------------- layer 1 GEMM: xl1 = x @ W1 (+ attention scores), fp16 out -----
__global__ void k_gemm1(const float* __restrict__ x, const float* __restrict__ W1,
                        const float* __restrict__ as, const float* __restrict__ ad) {
    __shared__ float xsh[16 * 128];
    int tid = threadIdx.x;
    int base = blockIdx.x * 16;
    {
        float4* d4 = (float4*)xsh;
        const float4* s4 = (const float4*)(x + (long)base * 128);
        for (int i = tid; i < 512; i += 128) d4[i] = s4[i];
    }
    __syncthreads();
    int nl = tid >> 4, t4 = tid & 15;
    const ulonglong2* W4 = (const ulonglong2*)W1;   // {w01,w23} packed f32x2 pairs
    unsigned long long aA0 = 0, aA1 = 0, aB0 = 0, aB1 = 0;
    const float* xa = &xsh[nl * 128];
    const float* xb = &xsh[(nl + 8) * 128];
    #pragma unroll 4
    for (int k = 0; k < 128; k++) {
        ulonglong2 w = W4[k * 16 + t4];
        unsigned long long va = pk2(xa[k], xa[k]);
        unsigned long long vb = pk2(xb[k], xb[k]);
        aA0 = ffma2(va, w.x, aA0); aA1 = ffma2(va, w.y, aA1);
        aB0 = ffma2(vb, w.x, aB0); aB1 = ffma2(vb, w.y, aB1);
    }
    float2 A0 = upk2(aA0), A1 = upk2(aA1), B0 = upk2(aB0), B1 = upk2(aB1);
    int nA = base + nl, nB = base + nl + 8;
    {
        __half2 a01 = __floats2half2_rn(A0.x, A0.y);
        __half2 a23 = __floats2half2_rn(A1.x, A1.y);
        __half2 b01 = __floats2half2_rn(B0.x, B0.y);
        __half2 b23 = __floats2half2_rn(B1.x, B1.y);
        uint2 pa, pb;
        pa.x = *(unsigned*)&a01; pa.y = *(unsigned*)&a23;
        pb.x = *(unsigned*)&b01; pb.y = *(unsigned*)&b23;
        ((uint2*)g_xl1h)[nA * 16 + t4] = pa;
        ((uint2*)g_xl1h)[nB * 16 + t4] = pb;
    }
    float4 a = ((const float4*)as)[t4];
    float4 d = ((const float4*)ad)[t4];
    float psA = A0.x * a.x + A0.y * a.y + A1.x * a.z + A1.y * a.w;
    float pdA = A0.x * d.x + A0.y * d.y + A1.x * d.z + A1.y * d.w;
    float psB = B0.x * a.x + B0.y * a.y + B1.x * a.z + B1.y * a.w;
    float pdB = B0.x * d.x + B0.y * d.y + B1.x * d.z + B1.y * d.w;
    #pragma unroll
    for (int o = 1; o < 8; o <<= 1) {
        psA += __shfl_xor_sync(0xffffffffu, psA, o);
        pdA += __shfl_xor_sync(0xffffffffu, pdA, o);
        psB += __shfl_xor_sync(0xffffffffu, psB, o);
        pdB += __shfl_xor_sync(0xffffffffu, pdB, o);
    }
    if ((t4 & 7) == 0) {
        int h = t4 >> 3;
        g_as1[nA * 2 + h] = psA;  g_ad1[nA * 2 + h] = pdA;
        g_as1[nB * 2 + h] = psB;  g_ad1[nB * 2 + h] = pdB;
    }
}

// ---------------- layer 1 aggregation: 1 warp/node, int4 bins, HFMA2 acc --------
__global__ void k_agg1(const float* __restrict__ b1) {
    int n = blockIdx.x * 8 + (threadIdx.x >> 5);
    int lane = threadIdx.x & 31;
    float2 adv2 = ((const float2*)g_ad1)[n];
    bool h0 = lane < 16;
    float adv = h0 ? adv2.x : adv2.y;
    float s = 0.f;
    __half2 acc = __float2half2_rn(0.f);
    const int* bin = &g_srcs[n * CAP];
    int cnt = g_cur[n];
    const __half2* X = (const __half2*)g_xl1h;   // row = 32 half2
    int j = 0;
    for (; j + 3 < cnt; j += 4) {
        int4 sv = *(const int4*)&bin[j];
        float2 q0 = ((const float2*)g_as1)[sv.x];
        float2 q1 = ((const float2*)g_as1)[sv.y];
        float2 q2 = ((const float2*)g_as1)[sv.z];
        float2 q3 = ((const float2*)g_as1)[sv.w];
        __half2 x0 = X[sv.x * 32 + lane];
        __half2 x1 = X[sv.y * 32 + lane];
        __half2 x2 = X[sv.z * 32 + lane];
        __half2 x3 = X[sv.w * 32 + lane];
        float p0 = __expf(lrelu((h0 ? q0.x : q0.y) + adv));
        float p1 = __expf(lrelu((h0 ? q1.x : q1.y) + adv));
        float p2 = __expf(lrelu((h0 ? q2.x : q2.y) + adv));
        float p3 = __expf(lrelu((h0 ? q3.x : q3.y) + adv));
        s += (p0 + p1) + (p2 + p3);
        acc = __hfma2(__float2half2_rn(p0), x0, acc);
        acc = __hfma2(__float2half2_rn(p1), x1, acc);
        acc = __hfma2(__float2half2_rn(p2), x2, acc);
        acc = __hfma2(__float2half2_rn(p3), x3, acc);
    }
    for (; j < cnt; j++) {
        int s0 = bin[j];
        float2 q0 = ((const float2*)g_as1)[s0];
        __half2 x0 = X[s0 * 32 + lane];
        float p0 = __expf(lrelu((h0 ? q0.x : q0.y) + adv));
        s += p0;
        acc = __hfma2(__float2half2_rn(p0), x0, acc);
    }
    float inv = 1.f / s;
    float2 u = __half22float2(acc);
    float2 bb = ((const float2*)b1)[lane];
    float o0 = u.x * inv + bb.x;
    float o1 = u.y * inv + bb.y;
    o0 = o0 > 0.f ? o0 : (__expf(o0) - 1.f);
    o1 = o1 > 0.f ? o1 : (__expf(o1) - 1.f);
    ((float2*)g_h1)[n * 32 + lane] = make_float2(o0, o1);
}

// ---------------- layer 2 GEMM: xl2 = h1 @ W2 (+ scores), fp16 out ----------------
__global__ void k_gemm2(const float* __restrict__ W2, const float* __restrict__ as,
                        const float* __restrict__ ad) {
    __shared__ float hsh[8 * 64];
    int tid = threadIdx.x;
    int base = blockIdx.x * 8;
    {
        float4* d4 = (float4*)hsh;
        const float4* s4 = (const float4*)(g_h1 + (long)base * 64);
        if (tid < 128) d4[tid] = s4[tid];
    }
    __syncthreads();
    int nl = tid >> 5, t = tid & 31;
    const ulonglong2* W4 = (const ulonglong2*)W2;
    unsigned long long aA0 = 0, aA1 = 0, aB0 = 0, aB1 = 0;
    const float* xa = &hsh[nl * 64];
    const float* xb = &hsh[(nl + 4) * 64];
    #pragma unroll 4
    for (int k = 0; k < 64; k++) {
        ulonglong2 w = W4[k * 32 + t];
        unsigned long long va = pk2(xa[k], xa[k]);
        unsigned long long vb = pk2(xb[k], xb[k]);
        aA0 = ffma2(va, w.x, aA0); aA1 = ffma2(va, w.y, aA1);
        aB0 = ffma2(vb, w.x, aB0); aB1 = ffma2(vb, w.y, aB1);
    }
    float2 A0 = upk2(aA0), A1 = upk2(aA1), B0 = upk2(aB0), B1 = upk2(aB1);
    int nA = base + nl, nB = base + nl + 4;
    {
        __half2 a01 = __floats2half2_rn(A0.x, A0.y);
        __half2 a23 = __floats2half2_rn(A1.x, A1.y);
        __half2 b01 = __floats2half2_rn(B0.x, B0.y);
        __half2 b23 = __floats2half2_rn(B1.x, B1.y);
        uint2 pa, pb;
        pa.x = *(unsigned*)&a01; pa.y = *(unsigned*)&a23;
        pb.x = *(unsigned*)&b01; pb.y = *(unsigned*)&b23;
        ((uint2*)g_xl2h)[nA * 32 + t] = pa;
        ((uint2*)g_xl2h)[nB * 32 + t] = pb;
    }
    float4 a = ((const float4*)as)[t];
    float4 d = ((const float4*)ad)[t];
    float psA = A0.x * a.x + A0.y * a.y + A1.x * a.z + A1.y * a.w;
    float pdA = A0.x * d.x + A0.y * d.y + A1.x * d.z + A1.y * d.w;
    float psB = B0.x * a.x + B0.y * a.y + B1.x * a.z + B1.y * a.w;
    float pdB = B0.x * d.x + B0.y * d.y + B1.x * d.z + B1.y * d.w;
    #pragma unroll
    for (int o = 1; o < 32; o <<= 1) {
        psA += __shfl_xor_sync(0xffffffffu, psA, o);
        pdA += __shfl_xor_sync(0xffffffffu, pdA, o);
        psB += __shfl_xor_sync(0xffffffffu, psB, o);
        pdB += __shfl_xor_sync(0xffffffffu, pdB, o);
    }
    if (t == 0) {
        g_as2[nA] = psA; g_ad2[nA] = pdA;
        g_as2[nB] = psB; g_ad2[nB] = pdB;
    }
}

// ---------------- layer 2 aggregation: 2 warps/node, int4 bins, HFMA2 acc -------
__global__ void k_agg2(const float* __restrict__ b2, const void* __restrict__ batch) {
    int t = threadIdx.x;
    int n = blockIdx.x * 4 + (t >> 6);
    int w = (t >> 5) & 1;
    int lane = t & 31;
    int col = w * 32 + lane;                      // half2 index within row
    float adv = g_ad2[n];
    float s = 0.f;
    __half2 acc = __float2half2_rn(0.f);
    const int* bin = &g_srcs[n * CAP];
    int cnt = g_cur[n];
    const __half2* X = (const __half2*)g_xl2h;    // row = 64 half2
    int j = 0;
    for (; j + 3 < cnt; j += 4) {
        int4 sv = *(const int4*)&bin[j];
        float e0 = g_as2[sv.x], e1 = g_as2[sv.y], e2 = g_as2[sv.z], e3 = g_as2[sv.w];
        __half2 x0 = X[sv.x * 64 + col];
        __half2 x1 = X[sv.y * 64 + col];
        __half2 x2 = X[sv.z * 64 + col];
        __half2 x3 = X[sv.w * 64 + col];
        float p0 = __expf(lrelu(e0 + adv));
        float p1 = __expf(lrelu(e1 + adv));
        float p2 = __expf(lrelu(e2 + adv));
        float p3 = __expf(lrelu(e3 + adv));
        s += (p0 + p1) + (p2 + p3);
        acc = __hfma2(__float2half2_rn(p0), x0, acc);
        acc = __hfma2(__float2half2_rn(p1), x1, acc);
        acc = __hfma2(__float2half2_rn(p2), x2, acc);
        acc = __hfma2(__float2half2_rn(p3), x3, acc);
    }
    for (; j < cnt; j++) {
        int s0 = bin[j];
        float e0 = g_as2[s0];
        __half2 x0 = X[s0 * 64 + col];
        float p0 = __expf(lrelu(e0 + adv));
        s += p0;
        acc = __hfma2(__float2half2_rn(p0), x0, acc);
    }
    float inv = 1.f / s;
    float2 u = __half22float2(acc);
    float2 bb = ((const float2*)b2)[col];
    float v0 = u.x * inv + bb.x; v0 = v0 > 0.f ? v0 : (__expf(v0) - 1.f);
    float v1 = u.y * inv + bb.y; v1 = v1 > 0.f ? v1 : (__expf(v1) - 1.f);
    int b = idx_at(batch, n);
    float* pp = &g_pool[b * 128 + col * 2];
    atomicAdd(pp + 0, v0);
    atomicAdd(pp + 1, v1);
    if (col == 0) atomicAdd(&g_cnt[b], 1);
}

// ---------------- final: mean pool -> out ----------------
__global__ void k_final(float* __restrict__ out) {
    int i = blockIdx.x * 256 + threadIdx.x;
    if (i < NG * 128) {
        int g = i >> 7;
        out[i] = g_pool[i] / fmaxf((float)g_cnt[g], 1.f);
    }
}

extern "C" void kernel_launch(void* const* d_in, const int* in_sizes, int n_in,
                              void* d_out, int out_size) {
    const float* x   = (const float*)d_in[0];
    const void*  ei  = d_in[1];
    const void*  bat = d_in[2];
    const float* W1  = (const float*)d_in[3];
    const float* as1 = (const float*)d_in[4];
    const float* ad1 = (const float*)d_in[5];
    const float* b1  = (const float*)d_in[6];
    const float* W2  = (const float*)d_in[7];
    const float* as2 = (const float*)d_in[8];
    const float* ad2 = (const float*)d_in[9];
    const float* b2  = (const float*)d_in[10];
    float* out = (float*)d_out;

    // 7 launches; ncu capture slot (#3) lands on k_agg1 — verifies the HFMA2 delta.
    k_init<<<NIB, 256>>>((const int*)ei);            // #0
    k_gemm1<<<NN / 16, 128>>>(x, W1, as1, ad1);      // #1
    k_fill<<<(NP + 255) / 256, 256>>>(ei);           // #2
    k_agg1<<<NN / 8, 256>>>(b1);                     // #3 <-- profiled
    k_gemm2<<<NN / 8, 128>>>(W2, as2, ad2);          // #4
    k_agg2<<<NN / 4, 256>>>(b2, bat);                // #5
    k_final<<<32, 256>>>(out);                       // #6
}

// round 11
// speedup vs baseline: 1.2712x; 1.2331x over previous
#include <cuda_runtime.h>
#include <cuda_fp16.h>

#define NN 50000
#define NE 1600000
#define NP (NE / 2)              // 800000 edge pairs
#define NG 64
#define CAP 128                  // per-node bin capacity (Poisson(32): P(>=127) ~ 1e-43)
#define NIB ((NN + 255) / 256)   // init blocks
#define LOG2E 1.4426950408889634f

// ---------------- scratch (static device globals; no allocation) ----------------
__device__ __align__(16) __half g_xl1h[NN * 64];
__device__ __align__(16) __half g_xl2h[NN * 128];
__device__ float g_as1[NN * 2];   // pre-scaled by LOG2E
__device__ float g_ad1[NN * 2];   // pre-scaled by LOG2E
__device__ float g_h1[NN * 64];
__device__ float g_as2[NN];       // pre-scaled by LOG2E
__device__ float g_ad2[NN];       // pre-scaled by LOG2E
__device__ int   g_cur[NN];          // per-node count (starts at 1: self loop)
__device__ __align__(16) int g_srcs[NN * CAP];   // binned adjacency, 25.6 MB
__device__ float g_pool[NG * 128];
__device__ int   g_cnt[NG];
__device__ int   g_is64;

// ---------------- f32x2 packed helpers ----------------
__device__ __forceinline__ unsigned long long pk2(float x, float y) {
    unsigned long long r;
    asm("mov.b64 %0,{%1,%2};" : "=l"(r) : "f"(x), "f"(y));
    return r;
}
__device__ __forceinline__ float2 upk2(unsigned long long v) {
    float x, y;
    asm("mov.b64 {%0,%1},%2;" : "=f"(x), "=f"(y) : "l"(v));
    return make_float2(x, y);
}
__device__ __forceinline__ unsigned long long ffma2(unsigned long long a,
                                                    unsigned long long b,
                                                    unsigned long long c) {
    unsigned long long d;
    asm("fma.rn.f32x2 %0,%1,%2,%3;" : "=l"(d) : "l"(a), "l"(b), "l"(c));
    return d;
}

__device__ __forceinline__ int idx_at(const void* p, int i) {
    if (g_is64) return (int)((const long long*)p)[i];
    return ((const int*)p)[i];
}
__device__ __forceinline__ float lrelu(float e) { return fmaxf(e, 0.2f * e); }

// ---------------- init: seed self-loops, zero pool/cnt, dtype detect ------------
__global__ void k_init(const int* __restrict__ ei32) {
    int i = blockIdx.x * 256 + threadIdx.x;
    if (i < NN) {
        g_cur[i] = 1;
        g_srcs[i * CAP] = i;      // self loop in slot 0
    }
    if (i < NG * 128) g_pool[i] = 0.f;
    if (i < NG) g_cnt[i] = 0;
    if (i == 0) {
        int ok = 1;
        for (int k = 0; k < 64; k++)
            if (ei32[2 * k + 1] != 0) ok = 0;
        g_is64 = ok;
    }
}

// ---------------- direct binned scatter (no histogram, no scan) -----------------
__global__ void k_fill(const void* __restrict__ ei) {
    int t = blockIdx.x * 256 + threadIdx.x;
    if (t >= NP) return;
    int s0, s1, d0, d1;
    if (g_is64) {
        longlong2 sv = ((const longlong2*)ei)[t];
        longlong2 dv = ((const longlong2*)((const long long*)ei + NE))[t];
        s0 = (int)sv.x; s1 = (int)sv.y; d0 = (int)dv.x; d1 = (int)dv.y;
    } else {
        int2 sv = ((const int2*)ei)[t];
        int2 dv = ((const int2*)((const int*)ei + NE))[t];
        s0 = sv.x; s1 = sv.y; d0 = dv.x; d1 = dv.y;
    }
    int p0 = atomicAdd(&g_cur[d0], 1);
    g_srcs[d0 * CAP + p0] = s0;
    int p1 = atomicAdd(&g_cur[d1], 1);
    g_srcs[d1 * CAP + p1] = s1;
}

// ---------------- layer 1 GEMM: xl1 = x @ W1 (+ scaled attention scores) --------
__global__ void k_gemm1(const float* __restrict__ x, const float* __restrict__ W1,
                        const float* __restrict__ as, const float* __restrict__ ad) {
    __shared__ float xsh[16 * 128];
    int tid = threadIdx.x;
    int base = blockIdx.x * 16;
    {
        float4* d4 = (float4*)xsh;
        const float4* s4 = (const float4*)(x + (long)base * 128);
        for (int i = tid; i < 512; i += 128) d4[i] = s4[i];
    }
    __syncthreads();
    int nl = tid >> 4, t4 = tid & 15;
    const ulonglong2* W4 = (const ulonglong2*)W1;   // {w01,w23} packed f32x2 pairs
    unsigned long long aA0 = 0, aA1 = 0, aB0 = 0, aB1 = 0;
    const float* xa = &xsh[nl * 128];
    const float* xb = &xsh[(nl + 8) * 128];
    #pragma unroll 4
    for (int k = 0; k < 128; k++) {
        ulonglong2 w = W4[k * 16 + t4];
        unsigned long long va = pk2(xa[k], xa[k]);
        unsigned long long vb = pk2(xb[k], xb[k]);
        aA0 = ffma2(va, w.x, aA0); aA1 = ffma2(va, w.y, aA1);
        aB0 = ffma2(vb, w.x, aB0); aB1 = ffma2(vb, w.y, aB1);
    }
    float2 A0 = upk2(aA0), A1 = upk2(aA1), B0 = upk2(aB0), B1 = upk2(aB1);
    int nA = base + nl, nB = base + nl + 8;
    {
        __half2 a01 = __floats2half2_rn(A0.x, A0.y);
        __half2 a23 = __floats2half2_rn(A1.x, A1.y);
        __half2 b01 = __floats2half2_rn(B0.x, B0.y);
        __half2 b23 = __floats2half2_rn(B1.x, B1.y);
        uint2 pa, pb;
        pa.x = *(unsigned*)&a01; pa.y = *(unsigned*)&a23;
        pb.x = *(unsigned*)&b01; pb.y = *(unsigned*)&b23;
        ((uint2*)g_xl1h)[nA * 16 + t4] = pa;
        ((uint2*)g_xl1h)[nB * 16 + t4] = pb;
    }
    float4 a = ((const float4*)as)[t4];
    float4 d = ((const float4*)ad)[t4];
    float psA = A0.x * a.x + A0.y * a.y + A1.x * a.z + A1.y * a.w;
    float pdA = A0.x * d.x + A0.y * d.y + A1.x * d.z + A1.y * d.w;
    float psB = B0.x * a.x + B0.y * a.y + B1.x * a.z + B1.y * a.w;
    float pdB = B0.x * d.x + B0.y * d.y + B1.x * d.z + B1.y * d.w;
    #pragma unroll
    for (int o = 1; o < 8; o <<= 1) {
        psA += __shfl_xor_sync(0xffffffffu, psA, o);
        pdA += __shfl_xor_sync(0xffffffffu, pdA, o);
        psB += __shfl_xor_sync(0xffffffffu, psB, o);
        pdB += __shfl_xor_sync(0xffffffffu, pdB, o);
    }
    if ((t4 & 7) == 0) {
        int h = t4 >> 3;
        g_as1[nA * 2 + h] = psA * LOG2E;  g_ad1[nA * 2 + h] = pdA * LOG2E;
        g_as1[nB * 2 + h] = psB * LOG2E;  g_ad1[nB * 2 + h] = pdB * LOG2E;
    }
}

// ---------------- layer 1 aggregation: smem score phase + 4-edge gather ---------
__global__ void k_agg1(const float* __restrict__ b1) {
    __shared__ float2 sp[8][CAP];    // 8 warps x 128 x 8B = 8 KB
    int wwarp = threadIdx.x >> 5;
    int n = blockIdx.x * 8 + wwarp;
    int lane = threadIdx.x & 31;
    float2 adv = ((const float2*)g_ad1)[n];
    const int* bin = &g_srcs[n * CAP];
    int cnt = g_cur[n];
    // phase 1: lane-parallel edge scores (scores are pre-scaled by LOG2E)
    for (int j = lane; j < cnt; j += 32) {
        int src = bin[j];
        float2 q = ((const float2*)g_as1)[src];
        float e0 = lrelu(q.x + adv.x);
        float e1 = lrelu(q.y + adv.y);
        sp[wwarp][j] = make_float2(exp2f(e0), exp2f(e1));
    }
    __syncwarp();
    // phase 2: gather
    bool h0 = lane < 16;
    float s = 0.f;
    unsigned long long acc = 0;
    const __half2* X = (const __half2*)g_xl1h;   // row = 32 half2
    int j = 0;
    for (; j + 3 < cnt; j += 4) {
        int4 sv = *(const int4*)&bin[j];
        float2 r0 = sp[wwarp][j],     r1 = sp[wwarp][j + 1];
        float2 r2 = sp[wwarp][j + 2], r3 = sp[wwarp][j + 3];
        __half2 x0 = X[sv.x * 32 + lane];
        __half2 x1 = X[sv.y * 32 + lane];
        __half2 x2 = X[sv.z * 32 + lane];
        __half2 x3 = X[sv.w * 32 + lane];
        float p0 = h0 ? r0.x : r0.y;
        float p1 = h0 ? r1.x : r1.y;
        float p2 = h0 ? r2.x : r2.y;
        float p3 = h0 ? r3.x : r3.y;
        s += (p0 + p1) + (p2 + p3);
        float2 f0 = __half22float2(x0), f1 = __half22float2(x1);
        float2 f2 = __half22float2(x2), f3 = __half22float2(x3);
        acc = ffma2(pk2(p0, p0), pk2(f0.x, f0.y), acc);
        acc = ffma2(pk2(p1, p1), pk2(f1.x, f1.y), acc);
        acc = ffma2(pk2(p2, p2), pk2(f2.x, f2.y), acc);
        acc = ffma2(pk2(p3, p3), pk2(f3.x, f3.y), acc);
    }
    for (; j < cnt; j++) {
        int s0 = bin[j];
        float2 r0 = sp[wwarp][j];
        __half2 x0 = X[s0 * 32 + lane];
        float p0 = h0 ? r0.x : r0.y;
        s += p0;
        float2 f0 = __half22float2(x0);
        acc = ffma2(pk2(p0, p0), pk2(f0.x, f0.y), acc);
    }
    float inv = 1.f / s;
    float2 u = upk2(acc);
    float2 bb = ((const float2*)b1)[lane];
    float o0 = u.x * inv + bb.x;
    float o1 = u.y * inv + bb.y;
    o0 = o0 > 0.f ? o0 : (__expf(o0) - 1.f);
    o1 = o1 > 0.f ? o1 : (__expf(o1) - 1.f);
    ((float2*)g_h1)[n * 32 + lane] = make_float2(o0, o1);
}

// ---------------- layer 2 GEMM: xl2 = h1 @ W2 (+ scaled scores), fp16 out -------
__global__ void k_gemm2(const float* __restrict__ W2, const float* __restrict__ as,
                        const float* __restrict__ ad) {
    __shared__ float hsh[8 * 64];
    int tid = threadIdx.x;
    int base = blockIdx.x * 8;
    {
        float4* d4 = (float4*)hsh;
        const float4* s4 = (const float4*)(g_h1 + (long)base * 64);
        if (tid < 128) d4[tid] = s4[tid];
    }
    __syncthreads();
    int nl = tid >> 5, t = tid & 31;
    const ulonglong2* W4 = (const ulonglong2*)W2;
    unsigned long long aA0 = 0, aA1 = 0, aB0 = 0, aB1 = 0;
    const float* xa = &hsh[nl * 64];
    const float* xb = &hsh[(nl + 4) * 64];
    #pragma unroll 4
    for (int k = 0; k < 64; k++) {
        ulonglong2 w = W4[k * 32 + t];
        unsigned long long va = pk2(xa[k], xa[k]);
        unsigned long long vb = pk2(xb[k], xb[k]);
        aA0 = ffma2(va, w.x, aA0); aA1 = ffma2(va, w.y, aA1);
        aB0 = ffma2(vb, w.x, aB0); aB1 = ffma2(vb, w.y, aB1);
    }
    float2 A0 = upk2(aA0), A1 = upk2(aA1), B0 = upk2(aB0), B1 = upk2(aB1);
    int nA = base + nl, nB = base + nl + 4;
    {
        __half2 a01 = __floats2half2_rn(A0.x, A0.y);
        __half2 a23 = __floats2half2_rn(A1.x, A1.y);
        __half2 b01 = __floats2half2_rn(B0.x, B0.y);
        __half2 b23 = __floats2half2_rn(B1.x, B1.y);
        uint2 pa, pb;
        pa.x = *(unsigned*)&a01; pa.y = *(unsigned*)&a23;
        pb.x = *(unsigned*)&b01; pb.y = *(unsigned*)&b23;
        ((uint2*)g_xl2h)[nA * 32 + t] = pa;
        ((uint2*)g_xl2h)[nB * 32 + t] = pb;
    }
    float4 a = ((const float4*)as)[t];
    float4 d = ((const float4*)ad)[t];
    float psA = A0.x * a.x + A0.y * a.y + A1.x * a.z + A1.y * a.w;
    float pdA = A0.x * d.x + A0.y * d.y + A1.x * d.z + A1.y * d.w;
    float psB = B0.x * a.x + B0.y * a.y + B1.x * a.z + B1.y * a.w;
    float pdB = B0.x * d.x + B0.y * d.y + B1.x * d.z + B1.y * d.w;
    #pragma unroll
    for (int o = 1; o < 32; o <<= 1) {
        psA += __shfl_xor_sync(0xffffffffu, psA, o);
        pdA += __shfl_xor_sync(0xffffffffu, pdA, o);
        psB += __shfl_xor_sync(0xffffffffu, psB, o);
        pdB += __shfl_xor_sync(0xffffffffu, pdB, o);
    }
    if (t == 0) {
        g_as2[nA] = psA * LOG2E; g_ad2[nA] = pdA * LOG2E;
        g_as2[nB] = psB * LOG2E; g_ad2[nB] = pdB * LOG2E;
    }
}

// ---------------- layer 2 aggregation: smem score phase + 2 warps/node ----------
__global__ void k_agg2(const float* __restrict__ b2, const void* __restrict__ batch) {
    __shared__ float sp[4][CAP];     // 4 nodes x 128 x 4B = 2 KB
    int t = threadIdx.x;
    int node_l = t >> 6;                          // 0..3
    int n = blockIdx.x * 4 + node_l;
    int w = (t >> 5) & 1;
    int lane = t & 31;
    int col = w * 32 + lane;                      // half2 index within row
    float adv = g_ad2[n];
    const int* bin = &g_srcs[n * CAP];
    int cnt = g_cur[n];
    // phase 1: 64 threads of this node compute scores lane-parallel
    for (int j = (t & 63); j < cnt; j += 64) {
        int src = bin[j];
        sp[node_l][j] = exp2f(lrelu(g_as2[src] + adv));
    }
    __syncthreads();
    // phase 2: gather
    float s = 0.f;
    unsigned long long acc = 0;
    const __half2* X = (const __half2*)g_xl2h;    // row = 64 half2
    int j = 0;
    for (; j + 3 < cnt; j += 4) {
        int4 sv = *(const int4*)&bin[j];
        float p0 = sp[node_l][j],     p1 = sp[node_l][j + 1];
        float p2 = sp[node_l][j + 2], p3 = sp[node_l][j + 3];
        __half2 x0 = X[sv.x * 64 + col];
        __half2 x1 = X[sv.y * 64 + col];
        __half2 x2 = X[sv.z * 64 + col];
        __half2 x3 = X[sv.w * 64 + col];
        s += (p0 + p1) + (p2 + p3);
        float2 f0 = __half22float2(x0), f1 = __half22float2(x1);
        float2 f2 = __half22float2(x2), f3 = __half22float2(x3);
        acc = ffma2(pk2(p0, p0), pk2(f0.x, f0.y), acc);
        acc = ffma2(pk2(p1, p1), pk2(f1.x, f1.y), acc);
        acc = ffma2(pk2(p2, p2), pk2(f2.x, f2.y), acc);
        acc = ffma2(pk2(p3, p3), pk2(f3.x, f3.y), acc);
    }
    for (; j < cnt; j++) {
        int s0 = bin[j];
        float p0 = sp[node_l][j];
        __half2 x0 = X[s0 * 64 + col];
        s += p0;
        float2 f0 = __half22float2(x0);
        acc = ffma2(pk2(p0, p0), pk2(f0.x, f0.y), acc);
    }
    float inv = 1.f / s;
    float2 u = upk2(acc);
    float2 bb = ((const float2*)b2)[col];
    float v0 = u.x * inv + bb.x; v0 = v0 > 0.f ? v0 : (__expf(v0) - 1.f);
    float v1 = u.y * inv + bb.y; v1 = v1 > 0.f ? v1 : (__expf(v1) - 1.f);
    int b = idx_at(batch, n);
    float* pp = &g_pool[b * 128 + col * 2];
    atomicAdd(pp + 0, v0);
    atomicAdd(pp + 1, v1);
    if (col == 0) atomicAdd(&g_cnt[b], 1);
}

// ---------------- final: mean pool -> out ----------------
__global__ void k_final(float* __restrict__ out) {
    int i = blockIdx.x * 256 + threadIdx.x;
    if (i < NG * 128) {
        int g = i >> 7;
        out[i] = g_pool[i] / fmaxf((float)g_cnt[g], 1.f);
    }
}

extern "C" void kernel_launch(void* const* d_in, const int* in_sizes, int n_in,
                              void* d_out, int out_size) {
    const float* x   = (const float*)d_in[0];
    const void*  ei  = d_in[1];
    const void*  bat = d_in[2];
    const float* W1  = (const float*)d_in[3];
    const float* as1 = (const float*)d_in[4];
    const float* ad1 = (const float*)d_in[5];
    const float* b1  = (const float*)d_in[6];
    const float* W2  = (const float*)d_in[7];
    const float* as2 = (const float*)d_in[8];
    const float* ad2 = (const float*)d_in[9];
    const float* b2  = (const float*)d_in[10];
    float* out = (float*)d_out;

    // 7 launches; ncu capture slot (#3) lands on k_agg1 — verifies the smem-score delta.
    k_init<<<NIB, 256>>>((const int*)ei);            // #0
    k_gemm1<<<NN / 16, 128>>>(x, W1, as1, ad1);      // #1
    k_fill<<<(NP + 255) / 256, 256>>>(ei);           // #2
    k_agg1<<<NN / 8, 256>>>(b1);                     // #3 <-- profiled
    k_gemm2<<<NN / 8, 128>>>(W2, as2, ad2);          // #4
    k_agg2<<<NN / 4, 256>>>(b2, bat);                // #5
    k_final<<<32, 256>>>(out);                       // #6
}